// round 13
// baseline (speedup 1.0000x reference)
#include <cuda_runtime.h>

// ComNet: R=64 runs, T=256 timesteps, N=1024 agents, MLP 4->10(tanh)->2.
// STAGGERED wavefront, skew-1, B=8: row t's block b covers agents
// [8b-t, 8b-t+7]. Producer (t-1) block b == consumer (t, block b) right-deps
// element-for-element -> inter-thread skew 1, total steps 415.
// One CTA per run, 256 threads, shuffles + 2-phase smem ring + one
// __syncthreads per step. MUFU tanh.

#define R_ 64
#define T_ 256
#define N_ 1024
#define B_ 8
#define NSTEP_ 415     // max_t (floor((1023+t)/8) + t) + 1 = 159 + 255 + 1

__device__ __forceinline__ float htanh(float x) {
    float r; asm("tanh.approx.f32 %0, %1;" : "=f"(r) : "f"(x)); return r;
}
__device__ __forceinline__ int clampN(int a) {
    return a < 0 ? 0 : (a > N_ - 1 ? N_ - 1 : a);
}

__global__ __launch_bounds__(256, 1)
void comnet_kernel(const float* __restrict__ runs,
                   const float* __restrict__ comm0,
                   const float* __restrict__ w1,
                   const float* __restrict__ b1,
                   const float* __restrict__ w2,
                   const float* __restrict__ b2,
                   float* __restrict__ out)
{
    const int r    = blockIdx.x;
    const int t    = threadIdx.x;
    const int lane = t & 31;
    const int warp = t >> 5;

    // 2-phase ring: producer lane31 writes phase s&1 at its step s; consumer
    // lane0 of next warp reads at step s+1 from phase (s-1)&1 == (s+1+... )
    __shared__ float4 ring[2][8][2];

    // ---- weights in registers ----
    float W1[40], B1[10], W2[20];
#pragma unroll
    for (int k = 0; k < 40; ++k) W1[k] = w1[k];
#pragma unroll
    for (int k = 0; k < 10; ++k) B1[k] = b1[k];
#pragma unroll
    for (int k = 0; k < 20; ++k) W2[k] = w2[k];
    const float B2lo = b2[0];
    const float B2hi = b2[1];

    const float2* __restrict__ xrow2 =
        (const float2*)(runs + ((size_t)r * T_ + t) * (size_t)N_ * 2);
    float* __restrict__ orow = out + ((size_t)r * T_ + t) * N_;
    const float* __restrict__ c0row = comm0 + (size_t)r * N_;

    // own block @ s-1 (8 comm values, two float4)
    float4 h1a = make_float4(0.f, 0.f, 0.f, 0.f);
    float4 h1b = h1a;

    // prefetch for step 0: agents A0 = -9t .. -9t+7 (clamped; real for t=0)
    float2 px[8];
    float  pc[8];
#pragma unroll
    for (int k = 0; k < 8; ++k) px[k] = xrow2[clampN(-9 * t + k)];
    if (t == 0) {
#pragma unroll
        for (int k = 0; k < 8; ++k) pc[k] = c0row[clampN(k + 1)];
    }

    for (int s = 0; s < NSTEP_; ++s) {
        const int b = s - t;
        const int A = 8 * b - t;                   // first agent of own block
        const bool active = (b >= 0) && (A <= N_ - 1) && (A >= -(B_ - 1));

        // ---- right values: producer (t-1) block b, elementwise ----
        float rt[8];
        rt[0] = __shfl_up_sync(0xffffffffu, h1a.x, 1);
        rt[1] = __shfl_up_sync(0xffffffffu, h1a.y, 1);
        rt[2] = __shfl_up_sync(0xffffffffu, h1a.z, 1);
        rt[3] = __shfl_up_sync(0xffffffffu, h1a.w, 1);
        rt[4] = __shfl_up_sync(0xffffffffu, h1b.x, 1);
        rt[5] = __shfl_up_sync(0xffffffffu, h1b.y, 1);
        rt[6] = __shfl_up_sync(0xffffffffu, h1b.z, 1);
        rt[7] = __shfl_up_sync(0xffffffffu, h1b.w, 1);
        if (lane == 0 && warp > 0) {
            const float4 ga = ring[(s + 1) & 1][warp - 1][0];  // written @ s-1
            const float4 gb = ring[(s + 1) & 1][warp - 1][1];
            rt[0] = ga.x; rt[1] = ga.y; rt[2] = ga.z; rt[3] = ga.w;
            rt[4] = gb.x; rt[5] = gb.y; rt[6] = gb.z; rt[7] = gb.w;
        }
        if (t == 0) {
#pragma unroll
            for (int k = 0; k < 8; ++k) rt[k] = pc[k];
        }

        float2 cx[8];
#pragma unroll
        for (int k = 0; k < 8; ++k) cx[k] = px[k];

        // ---- prefetch next step's block (A+8 .. A+15, clamped) ----
        {
            const int An = A + B_;
#pragma unroll
            for (int k = 0; k < 8; ++k) px[k] = xrow2[clampN(An + k)];
            if (t == 0) {
#pragma unroll
                for (int k = 0; k < 8; ++k) pc[k] = c0row[clampN(An + k + 1)];
            }
        }

        if (active) {
            float o1v[8];
            float lf = h1b.w;                       // c(t, A-1)
#pragma unroll
            for (int k = 0; k < 8; ++k) {
                const int a = A + k;                // agent index
                const float xx = cx[k].x;
                const float xy = cx[k].y;
                float rv = rt[k];
                rv = (a >= N_ - 1) ? 0.0f : rv;     // zero right boundary
                const float lfu = (a == 0) ? 0.0f : lf;  // zero left boundary

                float a0 = B2lo, a0b = 0.f, a1 = B2hi, a1b = 0.f;
#pragma unroll
                for (int j = 0; j < 10; ++j) {
                    float v = fmaf(W1[4 * j + 0], xx,  B1[j]);
                    v       = fmaf(W1[4 * j + 1], xy,  v);
                    v       = fmaf(W1[4 * j + 3], rv,  v);
                    v       = fmaf(W1[4 * j + 2], lfu, v);  // lf last: shortest chain
                    const float h = htanh(v);               // MUFU.TANH
                    if (j & 1) { a0b = fmaf(W2[j], h, a0b); a1b = fmaf(W2[10 + j], h, a1b); }
                    else       { a0  = fmaf(W2[j], h, a0);  a1  = fmaf(W2[10 + j], h, a1); }
                }
                const float o0 = a0 + a0b;
                const float o1 = a1 + a1b;
                if ((unsigned)a <= (unsigned)(N_ - 1)) orow[a] = o0;
                o1v[k] = o1;
                lf = o1;                            // left-chain within block
            }
            h1a = make_float4(o1v[0], o1v[1], o1v[2], o1v[3]);
            h1b = make_float4(o1v[4], o1v[5], o1v[6], o1v[7]);
            if (lane == 31) {
                ring[s & 1][warp][0] = h1a;
                ring[s & 1][warp][1] = h1b;
            }
        }

        __syncthreads();
    }
}

extern "C" void kernel_launch(void* const* d_in, const int* in_sizes, int n_in,
                              void* d_out, int out_size)
{
    const float* runs  = (const float*)d_in[0];
    const float* comm0 = (const float*)d_in[1];
    const float* w1    = (const float*)d_in[2];
    const float* b1    = (const float*)d_in[3];
    const float* w2    = (const float*)d_in[4];
    const float* b2    = (const float*)d_in[5];
    float* out = (float*)d_out;

    comnet_kernel<<<R_, T_>>>(runs, comm0, w1, b1, w2, b2, out);
}

// round 14
// speedup vs baseline: 1.1279x; 1.1279x over previous
#include <cuda_runtime.h>

// ComNet: R=64 runs, T=256 timesteps, N=1024 agents, MLP 4->10(tanh)->2.
// STAGGERED wavefront, skew-1, B=4 (R12), split into TWO barrier domains:
//   group1 = warps 0-3 (rows 0-127),  bar.sync 1,128 every step
//   group2 = warps 4-7 (rows 128-255), bar.sync 2,128 every step
// Cross-boundary (row 127 -> 128) has extra skew D=8: group2 blocks are
// b = s - t - 8, so warp4 lane0 reads a 16-deep ring slot written ~9 steps
// earlier by warp3 lane31. Drift between domains is bounded <=4 by a pairwise
// bar.sync 3,64 (warps 3,4) every 4th step; slack 9-4=5 keeps reads safe.
// Each SMSP hosts one warp of each domain -> two independent streams.

#define R_ 64
#define T_ 256
#define N_ 1024
#define D_ 8           // cross-group extra skew
#define NSTEP_ 583     // t=255: 255+8 + floor((1023+255)/4) + 1

__device__ __forceinline__ float htanh(float x) {
    float r; asm("tanh.approx.f32 %0, %1;" : "=f"(r) : "f"(x)); return r;
}
__device__ __forceinline__ int clampN(int a) {
    return a < 0 ? 0 : (a > N_ - 1 ? N_ - 1 : a);
}

__global__ __launch_bounds__(256, 1)
void comnet_kernel(const float* __restrict__ runs,
                   const float* __restrict__ comm0,
                   const float* __restrict__ w1,
                   const float* __restrict__ b1,
                   const float* __restrict__ w2,
                   const float* __restrict__ b2,
                   float* __restrict__ out)
{
    const int r    = blockIdx.x;
    const int t    = threadIdx.x;
    const int lane = t & 31;
    const int warp = t >> 5;
    const int off  = (warp >= 4) ? D_ : 0;     // group2 extra skew

    // intra-group 2-phase ring (skew-1 boundaries w0->1,1->2,2->3, 4->5,5->6,6->7)
    __shared__ float4 ring[2][8];
    // cross-group deep ring (row 127 -> 128), slack ~9 steps
    __shared__ float4 dring[16];

    // ---- weights in registers ----
    float W1[40], B1[10], W2[20];
#pragma unroll
    for (int k = 0; k < 40; ++k) W1[k] = w1[k];
#pragma unroll
    for (int k = 0; k < 10; ++k) B1[k] = b1[k];
#pragma unroll
    for (int k = 0; k < 20; ++k) W2[k] = w2[k];
    const float B2lo = b2[0];
    const float B2hi = b2[1];

    const float2* __restrict__ xrow2 =
        (const float2*)(runs + ((size_t)r * T_ + t) * (size_t)N_ * 2);
    float* __restrict__ orow = out + ((size_t)r * T_ + t) * N_;
    const float* __restrict__ c0row = comm0 + (size_t)r * N_;

    float4 h1 = make_float4(0.f, 0.f, 0.f, 0.f);   // own block @ s-1

    // prefetch for step 0: block b = -t-off -> A = -5t-4*off (clamped)
    float2 px[4];
    float  pc[4];
#pragma unroll
    for (int k = 0; k < 4; ++k) px[k] = xrow2[clampN(-5 * t - 4 * off + k)];
    if (t == 0) {
#pragma unroll
        for (int k = 0; k < 4; ++k) pc[k] = c0row[clampN(k + 1)];
    }

    __syncthreads();   // ring zero-state + weights visibility before split domains

    for (int s = 0; s < NSTEP_; ++s) {
        const int b = s - t - off;
        const int A = 4 * b - t;                   // first agent of own block
        const bool active = (b >= 0) && (A <= N_ - 1) && (A >= -3);

        // ---- right values: producer (t-1) block b == my rt, elementwise ----
        float r0 = __shfl_up_sync(0xffffffffu, h1.x, 1);
        float r1 = __shfl_up_sync(0xffffffffu, h1.y, 1);
        float r2 = __shfl_up_sync(0xffffffffu, h1.z, 1);
        float r3 = __shfl_up_sync(0xffffffffu, h1.w, 1);
        if (lane == 0 && warp > 0) {
            if (warp == 4) {
                // cross-group: row 127's block b was written at warp3's step
                // s_w = b + 127 = s - 9 (given off=8, skew 1)
                if (active) {
                    const float4 g = dring[(s - 9) & 15];
                    r0 = g.x; r1 = g.y; r2 = g.z; r3 = g.w;
                }
            } else {
                const float4 g = ring[(s + 1) & 1][warp - 1];  // written @ s-1
                r0 = g.x; r1 = g.y; r2 = g.z; r3 = g.w;
            }
        }
        if (t == 0) { r0 = pc[0]; r1 = pc[1]; r2 = pc[2]; r3 = pc[3]; }

        const float2 cx0 = px[0], cx1 = px[1], cx2 = px[2], cx3 = px[3];

        // ---- prefetch next step's block (A+4 .. A+7, clamped) ----
        {
            const int An = A + 4;
#pragma unroll
            for (int k = 0; k < 4; ++k) px[k] = xrow2[clampN(An + k)];
            if (t == 0) {
#pragma unroll
                for (int k = 0; k < 4; ++k) pc[k] = c0row[clampN(An + k + 1)];
            }
        }

        if (active) {
            float o1v[4];
            float lf = h1.w;                        // c(t, A-1)
#pragma unroll
            for (int k = 0; k < 4; ++k) {
                const int a = A + k;                // agent index
                const float xx = (k == 0) ? cx0.x : (k == 1) ? cx1.x
                                : (k == 2) ? cx2.x : cx3.x;
                const float xy = (k == 0) ? cx0.y : (k == 1) ? cx1.y
                                : (k == 2) ? cx2.y : cx3.y;
                float rt = (k == 0) ? r0 : (k == 1) ? r1
                          : (k == 2) ? r2 : r3;
                rt = (a >= N_ - 1) ? 0.0f : rt;     // zero right boundary
                const float lfu = (a == 0) ? 0.0f : lf;  // zero left boundary

                float a0 = B2lo, a0b = 0.f, a1 = B2hi, a1b = 0.f;
#pragma unroll
                for (int j = 0; j < 10; ++j) {
                    float v = fmaf(W1[4 * j + 0], xx,  B1[j]);
                    v       = fmaf(W1[4 * j + 1], xy,  v);
                    v       = fmaf(W1[4 * j + 3], rt,  v);
                    v       = fmaf(W1[4 * j + 2], lfu, v);  // lf last: shortest chain
                    const float h = htanh(v);               // MUFU.TANH
                    if (j & 1) { a0b = fmaf(W2[j], h, a0b); a1b = fmaf(W2[10 + j], h, a1b); }
                    else       { a0  = fmaf(W2[j], h, a0);  a1  = fmaf(W2[10 + j], h, a1); }
                }
                const float o0 = a0 + a0b;
                const float o1 = a1 + a1b;
                if ((unsigned)a <= (unsigned)(N_ - 1)) orow[a] = o0;
                o1v[k] = o1;
                lf = o1;                            // left-chain within block
            }
            const float4 cur = make_float4(o1v[0], o1v[1], o1v[2], o1v[3]);
            h1 = cur;
            if (lane == 31) {
                if (warp == 3)       dring[s & 15] = cur;        // cross-group
                else if (warp != 7)  ring[s & 1][warp] = cur;    // intra-group
            }
        }

        // ---- split barriers ----
        if (warp < 4) {
            if (warp == 3 && (s & 3) == 3)
                asm volatile("bar.sync 3, 64;" ::: "memory");    // drift bound
            asm volatile("bar.sync 1, 128;" ::: "memory");       // group1
        } else {
            if (warp == 4 && (s & 3) == 3)
                asm volatile("bar.sync 3, 64;" ::: "memory");    // drift bound
            asm volatile("bar.sync 2, 128;" ::: "memory");       // group2
        }
    }
}

extern "C" void kernel_launch(void* const* d_in, const int* in_sizes, int n_in,
                              void* d_out, int out_size)
{
    const float* runs  = (const float*)d_in[0];
    const float* comm0 = (const float*)d_in[1];
    const float* w1    = (const float*)d_in[2];
    const float* b1    = (const float*)d_in[3];
    const float* w2    = (const float*)d_in[4];
    const float* b2    = (const float*)d_in[5];
    float* out = (float*)d_out;

    comnet_kernel<<<R_, T_>>>(runs, comm0, w1, b1, w2, b2, out);
}

// round 15
// speedup vs baseline: 1.2318x; 1.0921x over previous
#include <cuda_runtime.h>

// ComNet: R=64 runs, T=256 timesteps, N=1024 agents, MLP 4->10(tanh)->2.
// STAGGERED wavefront, skew-1, B=4 (R12 skeleton): row t's block b covers
// agents [4b-t, 4b-t+3]; producer (t-1) block b == consumer right-deps.
// 575 steps, one CTA per run, shuffles + 2-phase ring + 1 barrier/step.
// Math: packed fma.rn.f32x2 (FFMA2) over hidden-unit pairs, MUFU tanh.

#define R_ 64
#define T_ 256
#define N_ 1024
#define NSTEP_ 575

typedef unsigned long long ull;

__device__ __forceinline__ float htanh(float x) {
    float r; asm("tanh.approx.f32 %0, %1;" : "=f"(r) : "f"(x)); return r;
}
__device__ __forceinline__ ull pk(float lo, float hi) {
    ull r; asm("mov.b64 %0, {%1, %2};" : "=l"(r) : "f"(lo), "f"(hi)); return r;
}
__device__ __forceinline__ void upk(float& lo, float& hi, ull v) {
    asm("mov.b64 {%0, %1}, %2;" : "=f"(lo), "=f"(hi) : "l"(v));
}
__device__ __forceinline__ ull fma2(ull a, ull b, ull c) {
    ull d; asm("fma.rn.f32x2 %0, %1, %2, %3;" : "=l"(d) : "l"(a), "l"(b), "l"(c));
    return d;
}
__device__ __forceinline__ int clampN(int a) {
    return a < 0 ? 0 : (a > N_ - 1 ? N_ - 1 : a);
}

__global__ __launch_bounds__(256, 1)
void comnet_kernel(const float* __restrict__ runs,
                   const float* __restrict__ comm0,
                   const float* __restrict__ w1,
                   const float* __restrict__ b1,
                   const float* __restrict__ w2,
                   const float* __restrict__ b2,
                   float* __restrict__ out)
{
    const int r    = blockIdx.x;
    const int t    = threadIdx.x;
    const int lane = t & 31;
    const int warp = t >> 5;

    __shared__ float4 ring[2][8];

    // ---- packed weights in registers (pair p = hidden units 2p, 2p+1) ----
    ull W1p[20], B1p[5], W2a[5], W2b[5];
#pragma unroll
    for (int p = 0; p < 5; ++p) {
#pragma unroll
        for (int q = 0; q < 4; ++q)
            W1p[4 * p + q] = pk(w1[4 * (2 * p) + q], w1[4 * (2 * p + 1) + q]);
        B1p[p] = pk(b1[2 * p], b1[2 * p + 1]);
        W2a[p] = pk(w2[2 * p],      w2[2 * p + 1]);
        W2b[p] = pk(w2[10 + 2 * p], w2[10 + 2 * p + 1]);
    }
    const ull B2lo0 = pk(b2[0], 0.0f);
    const ull B2hi0 = pk(b2[1], 0.0f);

    const float2* __restrict__ xrow2 =
        (const float2*)(runs + ((size_t)r * T_ + t) * (size_t)N_ * 2);
    float* __restrict__ orow = out + ((size_t)r * T_ + t) * N_;
    const float* __restrict__ c0row = comm0 + (size_t)r * N_;

    float4 h1 = make_float4(0.f, 0.f, 0.f, 0.f);   // own block @ s-1

    float2 px[4];
    float  pc[4];
#pragma unroll
    for (int k = 0; k < 4; ++k) px[k] = xrow2[clampN(-5 * t + k)];
    if (t == 0) {
#pragma unroll
        for (int k = 0; k < 4; ++k) pc[k] = c0row[clampN(k + 1)];
    }

    for (int s = 0; s < NSTEP_; ++s) {
        const int b = s - t;
        const int A = 4 * b - t;
        const bool active = (b >= 0) && (A <= N_ - 1) && (A >= -3);

        // ---- right values: producer (t-1) block b, elementwise ----
        float r0 = __shfl_up_sync(0xffffffffu, h1.x, 1);
        float r1 = __shfl_up_sync(0xffffffffu, h1.y, 1);
        float r2 = __shfl_up_sync(0xffffffffu, h1.z, 1);
        float r3 = __shfl_up_sync(0xffffffffu, h1.w, 1);
        if (lane == 0 && warp > 0) {
            const float4 g = ring[(s + 1) & 1][warp - 1];  // written at s-1
            r0 = g.x; r1 = g.y; r2 = g.z; r3 = g.w;
        }
        if (t == 0) { r0 = pc[0]; r1 = pc[1]; r2 = pc[2]; r3 = pc[3]; }

        const float2 cx0 = px[0], cx1 = px[1], cx2 = px[2], cx3 = px[3];

        // ---- prefetch next step's block ----
        {
            const int An = A + 4;
#pragma unroll
            for (int k = 0; k < 4; ++k) px[k] = xrow2[clampN(An + k)];
            if (t == 0) {
#pragma unroll
                for (int k = 0; k < 4; ++k) pc[k] = c0row[clampN(An + k + 1)];
            }
        }

        if (active) {
            float o1v[4];
            float lf = h1.w;                        // c(t, A-1)
#pragma unroll
            for (int k = 0; k < 4; ++k) {
                const int a = A + k;
                const float xx = (k == 0) ? cx0.x : (k == 1) ? cx1.x
                                : (k == 2) ? cx2.x : cx3.x;
                const float xy = (k == 0) ? cx0.y : (k == 1) ? cx1.y
                                : (k == 2) ? cx2.y : cx3.y;
                float rt = (k == 0) ? r0 : (k == 1) ? r1
                          : (k == 2) ? r2 : r3;
                rt = (a >= N_ - 1) ? 0.0f : rt;
                const float lfu = (a == 0) ? 0.0f : lf;

                const ull xx2 = pk(xx, xx);
                const ull xy2 = pk(xy, xy);
                const ull rt2 = pk(rt, rt);
                const ull lf2 = pk(lfu, lfu);

                ull A0 = B2lo0, A1 = B2hi0;
#pragma unroll
                for (int p = 0; p < 5; ++p) {
                    ull v = fma2(W1p[4 * p + 0], xx2, B1p[p]);
                    v     = fma2(W1p[4 * p + 1], xy2, v);
                    v     = fma2(W1p[4 * p + 3], rt2, v);
                    v     = fma2(W1p[4 * p + 2], lf2, v);   // lf last: shortest chain
                    float alo, ahi; upk(alo, ahi, v);
                    const ull hh = pk(htanh(alo), htanh(ahi));
                    A0 = fma2(W2a[p], hh, A0);
                    A1 = fma2(W2b[p], hh, A1);
                }
                float a0l, a0h, a1l, a1h;
                upk(a0l, a0h, A0);
                upk(a1l, a1h, A1);
                const float o0 = a0l + a0h;
                const float o1 = a1l + a1h;
                if ((unsigned)a <= (unsigned)(N_ - 1)) orow[a] = o0;
                o1v[k] = o1;
                lf = o1;                            // left-chain within block
            }
            const float4 cur = make_float4(o1v[0], o1v[1], o1v[2], o1v[3]);
            h1 = cur;
            if (lane == 31) ring[s & 1][warp] = cur;
        }

        __syncthreads();
    }
}

extern "C" void kernel_launch(void* const* d_in, const int* in_sizes, int n_in,
                              void* d_out, int out_size)
{
    const float* runs  = (const float*)d_in[0];
    const float* comm0 = (const float*)d_in[1];
    const float* w1    = (const float*)d_in[2];
    const float* b1    = (const float*)d_in[3];
    const float* w2    = (const float*)d_in[4];
    const float* b2    = (const float*)d_in[5];
    float* out = (float*)d_out;

    comnet_kernel<<<R_, T_>>>(runs, comm0, w1, b1, w2, b2, out);
}

// round 16
// speedup vs baseline: 1.4377x; 1.1672x over previous
#include <cuda_runtime.h>

// ComNet: R=64 runs, T=256 timesteps, N=1024 agents, MLP 4->10(tanh)->2.
// STAGGERED wavefront, skew-1, B=4, TWO ROWS PER THREAD:
// thread u owns rows (2u, 2u+1); at step s it computes block b = s-u of BOTH:
//   row 2u   right-deps = row 2u-1 block b  (thread u-1 @ s-1: shuffle/ring)
//   row 2u+1 right-deps = row 2u   block b  (same thread, SAME STEP, registers)
// One barrier step advances 2 rows -> NSTEP = 319 + 127 + 1 = 447.
// One CTA per run, 128 threads (4 warps). MUFU tanh.

#define R_ 64
#define T_ 256
#define N_ 1024
#define NSTEP_ 447

__device__ __forceinline__ float htanh(float x) {
    float r; asm("tanh.approx.f32 %0, %1;" : "=f"(r) : "f"(x)); return r;
}
__device__ __forceinline__ int clampN(int a) {
    return a < 0 ? 0 : (a > N_ - 1 ? N_ - 1 : a);
}

__global__ __launch_bounds__(128, 1)
void comnet_kernel(const float* __restrict__ runs,
                   const float* __restrict__ comm0,
                   const float* __restrict__ w1,
                   const float* __restrict__ b1,
                   const float* __restrict__ w2,
                   const float* __restrict__ b2,
                   float* __restrict__ out)
{
    const int r    = blockIdx.x;
    const int u    = threadIdx.x;      // owns rows 2u, 2u+1
    const int lane = u & 31;
    const int warp = u >> 5;           // 0..3

    // 2-phase ring: lane31's h1o (row 64w+63's last block) -> next warp lane0
    __shared__ float4 ring[2][4];

    // ---- weights in registers ----
    float W1[40], B1[10], W2[20];
#pragma unroll
    for (int k = 0; k < 40; ++k) W1[k] = w1[k];
#pragma unroll
    for (int k = 0; k < 10; ++k) B1[k] = b1[k];
#pragma unroll
    for (int k = 0; k < 20; ++k) W2[k] = w2[k];
    const float B2lo = b2[0];
    const float B2hi = b2[1];

    const int te = 2 * u, to = 2 * u + 1;
    const float2* __restrict__ xrow_e =
        (const float2*)(runs + ((size_t)r * T_ + te) * (size_t)N_ * 2);
    const float2* __restrict__ xrow_o =
        (const float2*)(runs + ((size_t)r * T_ + to) * (size_t)N_ * 2);
    float* __restrict__ orow_e = out + ((size_t)r * T_ + te) * N_;
    float* __restrict__ orow_o = out + ((size_t)r * T_ + to) * N_;
    const float* __restrict__ c0row = comm0 + (size_t)r * N_;

    float4 h1e = make_float4(0.f, 0.f, 0.f, 0.f);  // row 2u   block @ s-1
    float4 h1o = h1e;                              // row 2u+1 block @ s-1

    // prefetch step-0 inputs: block b = -u -> A_e = -6u, A_o = -6u-1
    float2 pxe[4], pxo[4];
    float  pc[4];
#pragma unroll
    for (int k = 0; k < 4; ++k) {
        pxe[k] = xrow_e[clampN(-6 * u + k)];
        pxo[k] = xrow_o[clampN(-6 * u - 1 + k)];
    }
    if (u == 0) {
#pragma unroll
        for (int k = 0; k < 4; ++k) pc[k] = c0row[clampN(k + 1)];
    }

    for (int s = 0; s < NSTEP_; ++s) {
        const int b   = s - u;
        const int Ae  = 4 * b - te;                // first agent, row 2u
        const int Ao  = Ae - 1;                    // first agent, row 2u+1
        const bool act_e = (b >= 0) && (Ae <= N_ - 1) && (Ae >= -3);
        const bool act_o = (b >= 0) && (Ao <= N_ - 1) && (Ao >= -3);

        // ---- row 2u right-deps: thread u-1's h1o (row 2u-1 block b) ----
        float r0 = __shfl_up_sync(0xffffffffu, h1o.x, 1);
        float r1 = __shfl_up_sync(0xffffffffu, h1o.y, 1);
        float r2 = __shfl_up_sync(0xffffffffu, h1o.z, 1);
        float r3 = __shfl_up_sync(0xffffffffu, h1o.w, 1);
        if (lane == 0 && warp > 0) {
            const float4 g = ring[(s + 1) & 1][warp - 1];  // written at s-1
            r0 = g.x; r1 = g.y; r2 = g.z; r3 = g.w;
        }
        if (u == 0) { r0 = pc[0]; r1 = pc[1]; r2 = pc[2]; r3 = pc[3]; }

        const float2 ex0 = pxe[0], ex1 = pxe[1], ex2 = pxe[2], ex3 = pxe[3];
        const float2 ox0 = pxo[0], ox1 = pxo[1], ox2 = pxo[2], ox3 = pxo[3];

        // ---- prefetch next step's blocks ----
        {
            const int An = Ae + 4;
#pragma unroll
            for (int k = 0; k < 4; ++k) {
                pxe[k] = xrow_e[clampN(An + k)];
                pxo[k] = xrow_o[clampN(An - 1 + k)];
            }
            if (u == 0) {
#pragma unroll
                for (int k = 0; k < 4; ++k) pc[k] = c0row[clampN(An + k + 1)];
            }
        }

        // ================= row 2u (even) =================
        float e1v[4];
        if (act_e) {
            float lf = h1e.w;
#pragma unroll
            for (int k = 0; k < 4; ++k) {
                const int a = Ae + k;
                const float xx = (k == 0) ? ex0.x : (k == 1) ? ex1.x
                                : (k == 2) ? ex2.x : ex3.x;
                const float xy = (k == 0) ? ex0.y : (k == 1) ? ex1.y
                                : (k == 2) ? ex2.y : ex3.y;
                float rt = (k == 0) ? r0 : (k == 1) ? r1
                          : (k == 2) ? r2 : r3;
                rt = (a >= N_ - 1) ? 0.0f : rt;
                const float lfu = (a == 0) ? 0.0f : lf;

                float a0 = B2lo, a0b = 0.f, a1 = B2hi, a1b = 0.f;
#pragma unroll
                for (int j = 0; j < 10; ++j) {
                    float v = fmaf(W1[4 * j + 0], xx,  B1[j]);
                    v       = fmaf(W1[4 * j + 1], xy,  v);
                    v       = fmaf(W1[4 * j + 3], rt,  v);
                    v       = fmaf(W1[4 * j + 2], lfu, v);
                    const float h = htanh(v);
                    if (j & 1) { a0b = fmaf(W2[j], h, a0b); a1b = fmaf(W2[10 + j], h, a1b); }
                    else       { a0  = fmaf(W2[j], h, a0);  a1  = fmaf(W2[10 + j], h, a1); }
                }
                const float o0 = a0 + a0b;
                const float o1 = a1 + a1b;
                if ((unsigned)a <= (unsigned)(N_ - 1)) orow_e[a] = o0;
                e1v[k] = o1;
                lf = o1;
            }
            h1e = make_float4(e1v[0], e1v[1], e1v[2], e1v[3]);
        } else {
            e1v[0] = h1e.x; e1v[1] = h1e.y; e1v[2] = h1e.z; e1v[3] = h1e.w;
        }

        // ================= row 2u+1 (odd): rt = row 2u same-step block =====
        if (act_o) {
            float o1v[4];
            float lf = h1o.w;
#pragma unroll
            for (int k = 0; k < 4; ++k) {
                const int a = Ao + k;
                const float xx = (k == 0) ? ox0.x : (k == 1) ? ox1.x
                                : (k == 2) ? ox2.x : ox3.x;
                const float xy = (k == 0) ? ox0.y : (k == 1) ? ox1.y
                                : (k == 2) ? ox2.y : ox3.y;
                float rt = e1v[k];                  // in-register right-dep
                rt = (a >= N_ - 1) ? 0.0f : rt;
                const float lfu = (a == 0) ? 0.0f : lf;

                float a0 = B2lo, a0b = 0.f, a1 = B2hi, a1b = 0.f;
#pragma unroll
                for (int j = 0; j < 10; ++j) {
                    float v = fmaf(W1[4 * j + 0], xx,  B1[j]);
                    v       = fmaf(W1[4 * j + 1], xy,  v);
                    v       = fmaf(W1[4 * j + 3], rt,  v);
                    v       = fmaf(W1[4 * j + 2], lfu, v);
                    const float h = htanh(v);
                    if (j & 1) { a0b = fmaf(W2[j], h, a0b); a1b = fmaf(W2[10 + j], h, a1b); }
                    else       { a0  = fmaf(W2[j], h, a0);  a1  = fmaf(W2[10 + j], h, a1); }
                }
                const float o0 = a0 + a0b;
                const float o1 = a1 + a1b;
                if ((unsigned)a <= (unsigned)(N_ - 1)) orow_o[a] = o0;
                o1v[k] = o1;
                lf = o1;
            }
            h1o = make_float4(o1v[0], o1v[1], o1v[2], o1v[3]);
            if (lane == 31 && warp < 3) ring[s & 1][warp] = h1o;
        }

        __syncthreads();
    }
}

extern "C" void kernel_launch(void* const* d_in, const int* in_sizes, int n_in,
                              void* d_out, int out_size)
{
    const float* runs  = (const float*)d_in[0];
    const float* comm0 = (const float*)d_in[1];
    const float* w1    = (const float*)d_in[2];
    const float* b1    = (const float*)d_in[3];
    const float* w2    = (const float*)d_in[4];
    const float* b2    = (const float*)d_in[5];
    float* out = (float*)d_out;

    comnet_kernel<<<R_, 128>>>(runs, comm0, w1, b1, w2, b2, out);
}